// round 11
// baseline (speedup 1.0000x reference)
#include <cuda_runtime.h>
#include <cuda_bf16.h>

// Problem constants (fixed by the dataset)
#define D_CH   256
#define GRID_H 384
#define GRID_W 384
#define TOK_PER_BLK 32

// Token-index map for the sparse grid: g_map[r*W+c] = token index or -1.
__device__ int g_map[GRID_H * GRID_W];

// ---------------------------------------------------------------------------
// Kernel 1: clear the map
// ---------------------------------------------------------------------------
__global__ void init_map_kernel() {
    int i = blockIdx.x * blockDim.x + threadIdx.x;
    if (i < GRID_H * GRID_W) g_map[i] = -1;
}

// ---------------------------------------------------------------------------
// Kernel 2: scatter token indices into the map
// ---------------------------------------------------------------------------
__global__ void scatter_kernel(const int* __restrict__ coords, int n) {
    int i = blockIdx.x * blockDim.x + threadIdx.x;
    if (i < n) {
        int r = coords[2 * i];
        int c = coords[2 * i + 1];
        g_map[r * GRID_W + c] = i;
    }
}

// ---------------------------------------------------------------------------
// Kernel 3: gather-conv with transposed (D, N) output.
//   Block: 256 threads, 32 tokens.
//   Phase A (gather): warp w handles tokens w*4..w*4+3; lanes span channels
//     (8 channels/thread, stride 32) -> every global load is a 128B-coalesced
//     row segment of tokens[j, :]. Results go to smem, channel-major, row
//     stride 33 floats (odd mod 32 => conflict-free scalar STS/LDS).
//   Phase B (store): warp w handles channels w*32..w*32+31; lanes span the 32
//     tokens -> 128B-coalesced stores to out[c*n + tok].
//   out[c, i] = bias[c] + sum_k w[c,k] * tokens[map[nbr_k(i)], c]
// ---------------------------------------------------------------------------
__global__ __launch_bounds__(256) void conv_kernel(
    const float* __restrict__ tokens,   // [N, 256]
    const int*   __restrict__ coords,   // [N, 2]
    const float* __restrict__ weight,   // [256, 1, 3, 3] -> [256][9]
    const float* __restrict__ bias,     // [256]
    float*       __restrict__ out,      // [256, N]  (channel-major!)
    int n)
{
    __shared__ float wT[9][D_CH];                 // wT[tap][channel]
    __shared__ float sOut[D_CH * 33];             // [channel][token], stride 33
    __shared__ int   nb[TOK_PER_BLK][9];          // neighbor index per (token, tap)

    const int tid     = threadIdx.x;
    const int lane    = tid & 31;
    const int warp    = tid >> 5;                 // 0..7
    const int tokbase = blockIdx.x * TOK_PER_BLK;

    // --- transposed weight load: wT[k][d] = weight[d*9 + k] ---
    #pragma unroll
    for (int i = tid; i < 9 * D_CH; i += 256) {
        int d = i & 255;
        int k = i >> 8;
        wT[k][d] = weight[d * 9 + k];
    }

    // --- neighbor-index table: 32 tokens x 9 taps ---
    for (int i = tid; i < TOK_PER_BLK * 9; i += 256) {
        int t   = i / 9;
        int k   = i % 9;
        int tok = tokbase + t;
        int idx = -1;
        if (tok < n) {
            int r  = coords[2 * tok];
            int c  = coords[2 * tok + 1];
            int rr = r + (k / 3) - 1;
            int cc = c + (k % 3) - 1;
            if (rr >= 0 && rr < GRID_H && cc >= 0 && cc < GRID_W)
                idx = g_map[rr * GRID_W + cc];
        }
        nb[t][k] = idx;
    }
    __syncthreads();

    // --- Phase A: gather + FMA. 4 tokens per warp, 8 channels per thread. ---
    float breg[8];
    #pragma unroll
    for (int m = 0; m < 8; m++) breg[m] = bias[lane + 32 * m];

    float acc[4][8];
    #pragma unroll
    for (int it = 0; it < 4; it++)
        #pragma unroll
        for (int m = 0; m < 8; m++) acc[it][m] = breg[m];

    #pragma unroll
    for (int k = 0; k < 9; k++) {
        float wr[8];
        #pragma unroll
        for (int m = 0; m < 8; m++) wr[m] = wT[k][lane + 32 * m];

        #pragma unroll
        for (int it = 0; it < 4; it++) {
            int t = warp * 4 + it;
            int j = nb[t][k];
            if (j >= 0) {
                const float* src = tokens + (size_t)j * D_CH + lane;
                #pragma unroll
                for (int m = 0; m < 8; m++)
                    acc[it][m] = fmaf(wr[m], __ldg(src + 32 * m), acc[it][m]);
            }
        }
    }

    // --- write to smem transpose buffer (conflict-free: stride 33) ---
    #pragma unroll
    for (int it = 0; it < 4; it++) {
        int t = warp * 4 + it;
        #pragma unroll
        for (int m = 0; m < 8; m++)
            sOut[(lane + 32 * m) * 33 + t] = acc[it][m];
    }
    __syncthreads();

    // --- Phase B: coalesced (D, N) stores. warp -> 32 channels, lane -> token ---
    const int tok = tokbase + lane;
    #pragma unroll 4
    for (int cc = 0; cc < 32; cc++) {
        int c = warp * 32 + cc;
        float v = sOut[c * 33 + lane];            // bank (c+lane)%32: conflict-free
        if (tok < n) out[(size_t)c * n + tok] = v;
    }
}

// ---------------------------------------------------------------------------
// Launch — inputs bound BY ELEMENT COUNT (robust to metadata.txt ordering):
//   tokens : N*256 = 16,777,216 fp32    coords : 2N = 131,072 int32
//   weight : 2,304 fp32                 bias   : 256 fp32
//   grid_h / grid_w : 1 each (ignored; compile-time constants)
// Output: fp32, shape (D, N) flattened  (NumPy mixed advanced-indexing:
//   conv[0,:,rows,cols] -> (N,D), .T -> (D,N)).
// ---------------------------------------------------------------------------
extern "C" void kernel_launch(void* const* d_in, const int* in_sizes, int n_in,
                              void* d_out, int out_size) {
    int tok_i = 0;
    for (int i = 1; i < n_in; i++)
        if (in_sizes[i] > in_sizes[tok_i]) tok_i = i;
    const float* tokens = (const float*)d_in[tok_i];
    const int n = in_sizes[tok_i] / D_CH;   // 65536

    const int*   coords = nullptr;
    const float* weight = nullptr;
    const float* bias   = nullptr;
    for (int i = 0; i < n_in; i++) {
        if (i == tok_i) continue;
        const int sz = in_sizes[i];
        if (sz == 2 * n)         coords = (const int*)d_in[i];
        else if (sz == 9 * D_CH) weight = (const float*)d_in[i];
        else if (sz == D_CH)     bias   = (const float*)d_in[i];
    }
    if (!coords || !weight || !bias) {   // defensive positional fallback
        tokens = (const float*)d_in[0];
        coords = (const int*)d_in[1];
        weight = (const float*)d_in[2];
        bias   = (const float*)d_in[3];
    }

    float* out = (float*)d_out;

    // 1. clear map
    init_map_kernel<<<(GRID_H * GRID_W + 255) / 256, 256>>>();
    // 2. scatter
    scatter_kernel<<<(n + 255) / 256, 256>>>(coords, n);
    // 3. conv-gather with transposed output
    int nblocks = (n + TOK_PER_BLK - 1) / TOK_PER_BLK;
    conv_kernel<<<nblocks, 256>>>(tokens, coords, weight, bias, out, n);
}

// round 12
// speedup vs baseline: 1.0003x; 1.0003x over previous
#include <cuda_runtime.h>
#include <cuda_bf16.h>

// Problem constants (fixed by the dataset)
#define D_CH   256
#define GRID_H 384
#define GRID_W 384
#define TOK_PER_BLK 32

// Token-index map for the sparse grid: g_map[r*W+c] = token index or -1.
__device__ int g_map[GRID_H * GRID_W];

// ---------------------------------------------------------------------------
// Kernel 1: clear the map
// ---------------------------------------------------------------------------
__global__ void init_map_kernel() {
    int i = blockIdx.x * blockDim.x + threadIdx.x;
    if (i < GRID_H * GRID_W) g_map[i] = -1;
}

// ---------------------------------------------------------------------------
// Kernel 2: scatter token indices into the map
// ---------------------------------------------------------------------------
__global__ void scatter_kernel(const int* __restrict__ coords, int n) {
    int i = blockIdx.x * blockDim.x + threadIdx.x;
    if (i < n) {
        int r = coords[2 * i];
        int c = coords[2 * i + 1];
        g_map[r * GRID_W + c] = i;
    }
}

// ---------------------------------------------------------------------------
// Kernel 3: gather-conv with transposed (D, N) output.
//   Block: 256 threads, 32 tokens.
//   Phase A (gather): warp w handles tokens w*4..w*4+3; lanes span channels
//     (8 channels/thread, stride 32) -> every global load is a 128B-coalesced
//     row segment of tokens[j, :]. Results go to smem, channel-major, row
//     stride 33 floats (odd mod 32 => conflict-free scalar STS/LDS).
//   Phase B (store): warp w handles channels w*32..w*32+31; lanes span the 32
//     tokens -> 128B-coalesced stores to out[c*n + tok].
//   out[c, i] = bias[c] + sum_k w[c,k] * tokens[map[nbr_k(i)], c]
// ---------------------------------------------------------------------------
__global__ __launch_bounds__(256) void conv_kernel(
    const float* __restrict__ tokens,   // [N, 256]
    const int*   __restrict__ coords,   // [N, 2]
    const float* __restrict__ weight,   // [256, 1, 3, 3] -> [256][9]
    const float* __restrict__ bias,     // [256]
    float*       __restrict__ out,      // [256, N]  (channel-major!)
    int n)
{
    __shared__ float wT[9][D_CH];                 // wT[tap][channel]
    __shared__ float sOut[D_CH * 33];             // [channel][token], stride 33
    __shared__ int   nb[TOK_PER_BLK][9];          // neighbor index per (token, tap)

    const int tid     = threadIdx.x;
    const int lane    = tid & 31;
    const int warp    = tid >> 5;                 // 0..7
    const int tokbase = blockIdx.x * TOK_PER_BLK;

    // --- transposed weight load: wT[k][d] = weight[d*9 + k] ---
    #pragma unroll
    for (int i = tid; i < 9 * D_CH; i += 256) {
        int d = i & 255;
        int k = i >> 8;
        wT[k][d] = weight[d * 9 + k];
    }

    // --- neighbor-index table: 32 tokens x 9 taps ---
    for (int i = tid; i < TOK_PER_BLK * 9; i += 256) {
        int t   = i / 9;
        int k   = i % 9;
        int tok = tokbase + t;
        int idx = -1;
        if (tok < n) {
            int r  = coords[2 * tok];
            int c  = coords[2 * tok + 1];
            int rr = r + (k / 3) - 1;
            int cc = c + (k % 3) - 1;
            if (rr >= 0 && rr < GRID_H && cc >= 0 && cc < GRID_W)
                idx = g_map[rr * GRID_W + cc];
        }
        nb[t][k] = idx;
    }
    __syncthreads();

    // --- Phase A: gather + FMA. 4 tokens per warp, 8 channels per thread. ---
    float breg[8];
    #pragma unroll
    for (int m = 0; m < 8; m++) breg[m] = bias[lane + 32 * m];

    float acc[4][8];
    #pragma unroll
    for (int it = 0; it < 4; it++)
        #pragma unroll
        for (int m = 0; m < 8; m++) acc[it][m] = breg[m];

    #pragma unroll
    for (int k = 0; k < 9; k++) {
        float wr[8];
        #pragma unroll
        for (int m = 0; m < 8; m++) wr[m] = wT[k][lane + 32 * m];

        #pragma unroll
        for (int it = 0; it < 4; it++) {
            int t = warp * 4 + it;
            int j = nb[t][k];
            if (j >= 0) {
                const float* src = tokens + (size_t)j * D_CH + lane;
                #pragma unroll
                for (int m = 0; m < 8; m++)
                    acc[it][m] = fmaf(wr[m], __ldg(src + 32 * m), acc[it][m]);
            }
        }
    }

    // --- write to smem transpose buffer (conflict-free: stride 33) ---
    #pragma unroll
    for (int it = 0; it < 4; it++) {
        int t = warp * 4 + it;
        #pragma unroll
        for (int m = 0; m < 8; m++)
            sOut[(lane + 32 * m) * 33 + t] = acc[it][m];
    }
    __syncthreads();

    // --- Phase B: coalesced (D, N) stores. warp -> 32 channels, lane -> token ---
    const int tok = tokbase + lane;
    #pragma unroll 4
    for (int cc = 0; cc < 32; cc++) {
        int c = warp * 32 + cc;
        float v = sOut[c * 33 + lane];            // bank (c+lane)%32: conflict-free
        if (tok < n) out[(size_t)c * n + tok] = v;
    }
}

// ---------------------------------------------------------------------------
// Launch — inputs bound BY ELEMENT COUNT (robust to metadata.txt ordering):
//   tokens : N*256 = 16,777,216 fp32    coords : 2N = 131,072 int32
//   weight : 2,304 fp32                 bias   : 256 fp32
//   grid_h / grid_w : 1 each (ignored; compile-time constants)
// Output: fp32, shape (D, N) flattened  (NumPy mixed advanced-indexing:
//   conv[0,:,rows,cols] -> (N,D), .T -> (D,N)).
// ---------------------------------------------------------------------------
extern "C" void kernel_launch(void* const* d_in, const int* in_sizes, int n_in,
                              void* d_out, int out_size) {
    int tok_i = 0;
    for (int i = 1; i < n_in; i++)
        if (in_sizes[i] > in_sizes[tok_i]) tok_i = i;
    const float* tokens = (const float*)d_in[tok_i];
    const int n = in_sizes[tok_i] / D_CH;   // 65536

    const int*   coords = nullptr;
    const float* weight = nullptr;
    const float* bias   = nullptr;
    for (int i = 0; i < n_in; i++) {
        if (i == tok_i) continue;
        const int sz = in_sizes[i];
        if (sz == 2 * n)         coords = (const int*)d_in[i];
        else if (sz == 9 * D_CH) weight = (const float*)d_in[i];
        else if (sz == D_CH)     bias   = (const float*)d_in[i];
    }
    if (!coords || !weight || !bias) {   // defensive positional fallback
        tokens = (const float*)d_in[0];
        coords = (const int*)d_in[1];
        weight = (const float*)d_in[2];
        bias   = (const float*)d_in[3];
    }

    float* out = (float*)d_out;

    // 1. clear map
    init_map_kernel<<<(GRID_H * GRID_W + 255) / 256, 256>>>();
    // 2. scatter
    scatter_kernel<<<(n + 255) / 256, 256>>>(coords, n);
    // 3. conv-gather with transposed output
    int nblocks = (n + TOK_PER_BLK - 1) / TOK_PER_BLK;
    conv_kernel<<<nblocks, 256>>>(tokens, coords, weight, bias, out, n);
}

// round 13
// speedup vs baseline: 1.7017x; 1.7012x over previous
#include <cuda_runtime.h>
#include <cuda_bf16.h>

// Problem constants (fixed by the dataset)
#define D_CH   256
#define GRID_H 384
#define GRID_W 384
#define TOK_PER_BLK 16

// Token-index map for the sparse grid: g_map[r*W+c] = token index or -1.
__device__ int g_map[GRID_H * GRID_W];

// ---------------------------------------------------------------------------
// Kernel 1: clear the map
// ---------------------------------------------------------------------------
__global__ void init_map_kernel() {
    int i = blockIdx.x * blockDim.x + threadIdx.x;
    if (i < GRID_H * GRID_W) g_map[i] = -1;
}

// ---------------------------------------------------------------------------
// Kernel 2: scatter token indices into the map
// ---------------------------------------------------------------------------
__global__ void scatter_kernel(const int* __restrict__ coords, int n) {
    int i = blockIdx.x * blockDim.x + threadIdx.x;
    if (i < n) {
        g_map[coords[2 * i] * GRID_W + coords[2 * i + 1]] = i;
    }
}

// ---------------------------------------------------------------------------
// Kernel 3: gather-conv, (D, N) output.
//   256 threads = 8 warps; 16 tokens/block, 2 tokens/warp.
//   Live taps compacted per token -> branch-free float4 gather loop:
//     per entry: 2x LDG.128 (token row) + 2x LDS.128 (weights) + 8 FMA.
//   Lane l holds channels {4l..4l+3, 128+4l..128+4l+3} (fp32 accum).
//   Transpose via smem sOut[channel][token] (stride 17), then warp-per-32-
//   channels coalesced stores to out[c*n + tok].
// ---------------------------------------------------------------------------
__global__ __launch_bounds__(256, 6) void conv_kernel(
    const float* __restrict__ tokens,   // [N, 256]
    const int*   __restrict__ coords,   // [N, 2]
    const float* __restrict__ weight,   // [256][9]
    const float* __restrict__ bias,     // [256]
    float*       __restrict__ out,      // [256, N]  (channel-major)
    int n)
{
    __shared__ float wT[9][D_CH];            // wT[tap][channel]   (9 KB)
    __shared__ float sOut[D_CH * 17];        // [channel][token]   (17 KB)
    __shared__ int   ent[TOK_PER_BLK][9];    // compacted (j<<4)|k entries
    __shared__ int   cnt[TOK_PER_BLK];

    const int tid     = threadIdx.x;
    const int lane    = tid & 31;
    const int warp    = tid >> 5;            // 0..7
    const int tokbase = blockIdx.x * TOK_PER_BLK;

    // --- transposed weight load: wT[k][d] = weight[d*9 + k] ---
    #pragma unroll
    for (int i = tid; i < 9 * D_CH; i += 256) {
        int d = i & 255;
        int k = i >> 8;
        wT[k][d] = weight[d * 9 + k];
    }

    // --- raw neighbor table: 16 tokens x 9 taps (parallel gmem probes) ---
    if (tid < TOK_PER_BLK * 9) {
        int t   = tid / 9;
        int k   = tid % 9;
        int tok = tokbase + t;
        int idx = -1;
        if (tok < n) {
            int r  = coords[2 * tok];
            int c  = coords[2 * tok + 1];
            int rr = r + (k / 3) - 1;
            int cc = c + (k % 3) - 1;
            if (rr >= 0 && rr < GRID_H && cc >= 0 && cc < GRID_W)
                idx = g_map[rr * GRID_W + cc];
        }
        ent[t][k] = idx;
    }
    __syncthreads();

    // --- in-place deterministic compaction (k ascending) ---
    if (tid < TOK_PER_BLK) {
        int w = 0;
        #pragma unroll
        for (int k = 0; k < 9; k++) {
            int j = ent[tid][k];
            if (j >= 0) ent[tid][w++] = (j << 4) | k;
        }
        cnt[tid] = w;
    }
    __syncthreads();

    // --- Phase A: branch-free compacted gather, float4 everywhere ---
    const float4* tok4  = reinterpret_cast<const float4*>(tokens);
    const float4* bias4 = reinterpret_cast<const float4*>(bias);
    const float4  b0 = bias4[lane];         // channels 4l..4l+3
    const float4  b1 = bias4[32 + lane];    // channels 128+4l..128+4l+3

    #pragma unroll
    for (int it = 0; it < 2; it++) {
        const int t = warp * 2 + it;
        float4 a0 = b0, a1 = b1;
        const int m = cnt[t];

        #pragma unroll 2
        for (int e = 0; e < m; e++) {
            int p = ent[t][e];
            int j = p >> 4;
            int k = p & 15;
            const float4* src = tok4 + (size_t)j * (D_CH / 4);
            float4 v0 = src[lane];
            float4 v1 = src[32 + lane];
            const float4* w4 = reinterpret_cast<const float4*>(&wT[k][0]);
            float4 w0 = w4[lane];
            float4 w1 = w4[32 + lane];
            a0.x = fmaf(w0.x, v0.x, a0.x);
            a0.y = fmaf(w0.y, v0.y, a0.y);
            a0.z = fmaf(w0.z, v0.z, a0.z);
            a0.w = fmaf(w0.w, v0.w, a0.w);
            a1.x = fmaf(w1.x, v1.x, a1.x);
            a1.y = fmaf(w1.y, v1.y, a1.y);
            a1.z = fmaf(w1.z, v1.z, a1.z);
            a1.w = fmaf(w1.w, v1.w, a1.w);
        }

        // transpose staging: sOut[channel][token], row stride 17
        const int c0 = 4 * lane;
        sOut[(c0 + 0) * 17 + t] = a0.x;
        sOut[(c0 + 1) * 17 + t] = a0.y;
        sOut[(c0 + 2) * 17 + t] = a0.z;
        sOut[(c0 + 3) * 17 + t] = a0.w;
        const int c1 = 128 + 4 * lane;
        sOut[(c1 + 0) * 17 + t] = a1.x;
        sOut[(c1 + 1) * 17 + t] = a1.y;
        sOut[(c1 + 2) * 17 + t] = a1.z;
        sOut[(c1 + 3) * 17 + t] = a1.w;
    }
    __syncthreads();

    // --- Phase B: coalesced (D, N) stores. Warp w -> channels 32w..32w+31.
    //     lane = (half, token): 2 channels x 16 tokens per instruction. ---
    const int t    = lane & 15;
    const int half = lane >> 4;
    const int tok  = tokbase + t;
    if (tok < n) {
        #pragma unroll
        for (int i = 0; i < 16; i++) {
            int c = warp * 32 + 2 * i + half;
            out[(size_t)c * n + tok] = sOut[c * 17 + t];
        }
    }
}

// ---------------------------------------------------------------------------
// Launch — inputs bound BY ELEMENT COUNT (robust to metadata.txt ordering):
//   tokens : N*256 = 16,777,216 fp32    coords : 2N = 131,072 int32
//   weight : 2,304 fp32                 bias   : 256 fp32
// Output: fp32 (D, N) flattened (NumPy mixed advanced-indexing semantics).
// ---------------------------------------------------------------------------
extern "C" void kernel_launch(void* const* d_in, const int* in_sizes, int n_in,
                              void* d_out, int out_size) {
    int tok_i = 0;
    for (int i = 1; i < n_in; i++)
        if (in_sizes[i] > in_sizes[tok_i]) tok_i = i;
    const float* tokens = (const float*)d_in[tok_i];
    const int n = in_sizes[tok_i] / D_CH;   // 65536

    const int*   coords = nullptr;
    const float* weight = nullptr;
    const float* bias   = nullptr;
    for (int i = 0; i < n_in; i++) {
        if (i == tok_i) continue;
        const int sz = in_sizes[i];
        if (sz == 2 * n)         coords = (const int*)d_in[i];
        else if (sz == 9 * D_CH) weight = (const float*)d_in[i];
        else if (sz == D_CH)     bias   = (const float*)d_in[i];
    }
    if (!coords || !weight || !bias) {   // defensive positional fallback
        tokens = (const float*)d_in[0];
        coords = (const int*)d_in[1];
        weight = (const float*)d_in[2];
        bias   = (const float*)d_in[3];
    }

    float* out = (float*)d_out;

    // 1. clear map
    init_map_kernel<<<(GRID_H * GRID_W + 255) / 256, 256>>>();
    // 2. scatter
    scatter_kernel<<<(n + 255) / 256, 256>>>(coords, n);
    // 3. conv-gather with transposed output
    int nblocks = (n + TOK_PER_BLK - 1) / TOK_PER_BLK;
    conv_kernel<<<nblocks, 256>>>(tokens, coords, weight, bias, out, n);
}